// round 1
// baseline (speedup 1.0000x reference)
#include <cuda_runtime.h>
#include <cstdint>
#include <math.h>

// ---------------------------------------------------------------------------
// HierarchicalMoELayer: B=8 S=1024 D_MODEL=512 D_FF=2048, E=64 experts, TOPK=2
// Pipeline: route (count/scan/assign) -> GEMM1(+GELU) -> GEMM2 -> combine
// GEMMs use TF32 mma.sync m16n8k8 with cvt.rna (round-to-nearest) for accuracy.
// ---------------------------------------------------------------------------

#define kNSUB 8
#define kE    64
#define kT    8192
#define kA    16384     /* assignments = T * TOPK */
#define kDM   512
#define kDF   2048
#define kCAP  1024

// --------------------------- device scratch (statics) ----------------------
__device__ int   g_cnt[kE];
__device__ int   g_cnt2[kE];
__device__ int   g_off[kE];
__device__ int   g_eid[kA];
__device__ int   g_slot[kA];      // assignment -> compacted row slot
__device__ int   g_rowtok[kA];    // slot -> token
__device__ float g_wa[kA];        // weight * valid per assignment
__device__ float g_h [(size_t)kA * kDF];   // 128 MB GEMM1 output (post-GELU)
__device__ float g_y2[(size_t)kA * kDM];   // 32 MB  GEMM2 output

// ------------------------------- routing -----------------------------------
__global__ void k_zero() {
    int i = threadIdx.x;
    if (i < kE) { g_cnt[i] = 0; g_cnt2[i] = 0; }
}

__global__ void k_count(const int* __restrict__ cat, const int* __restrict__ sub) {
    int a = blockIdx.x * 256 + threadIdx.x;
    if (a < kA) {
        int e = cat[a] * kNSUB + sub[a];
        g_eid[a] = e;
        atomicAdd(&g_cnt[e], 1);
    }
}

__global__ void k_scan() {
    if (threadIdx.x == 0) {
        int s = 0;
        for (int e = 0; e < kE; ++e) { g_off[e] = s; s += g_cnt[e]; }
    }
}

__global__ void k_assign(const float* __restrict__ w) {
    int a = blockIdx.x * 256 + threadIdx.x;
    if (a < kA) {
        int e    = g_eid[a];
        int pos  = atomicAdd(&g_cnt2[e], 1);
        int slot = g_off[e] + pos;
        g_slot[a]      = slot;
        g_rowtok[slot] = a >> 1;                    // token index
        g_wa[a]        = (pos < kCAP) ? w[a] : 0.f; // fold validity into weight
    }
}

// ------------------------------ TF32 helpers -------------------------------
__device__ __forceinline__ uint32_t f2tf32(float x) {
    uint32_t r;
    asm("cvt.rna.tf32.f32 %0, %1;" : "=r"(r) : "f"(x));
    return r;
}

__device__ __forceinline__ void mma_tf32(float* d, const uint32_t* a, const uint32_t* b) {
    asm volatile(
        "mma.sync.aligned.m16n8k8.row.col.f32.tf32.tf32.f32 "
        "{%0,%1,%2,%3},{%4,%5,%6,%7},{%8,%9},{%0,%1,%2,%3};\n"
        : "+f"(d[0]), "+f"(d[1]), "+f"(d[2]), "+f"(d[3])
        : "r"(a[0]), "r"(a[1]), "r"(a[2]), "r"(a[3]),
          "r"(b[0]), "r"(b[1]));
}

// ------------------------------- grouped GEMM ------------------------------
// MODE 0: A = gathered hidden rows, Out = g_h, apply bias+GELU (erf)
// MODE 1: A = g_h (contiguous compacted rows), Out = g_y2, apply bias only
// Tile: BM=128, BN=64, BK=32; 256 threads = 8 warps (4x2), warp tile 32x32.
template<int KTOT, int NTOT, int MODE>
__global__ void __launch_bounds__(256, 2)
k_gemm(const float* __restrict__ Xin,
       const float* __restrict__ Wt,
       const float* __restrict__ bias)
{
    __shared__ uint32_t As[128 * 36];  // [m][k] padded: stride 36 -> conflict-free frags
    __shared__ uint32_t Bs[32 * 72];   // [k][n] padded: stride 72 -> conflict-free frags

    const int e    = blockIdx.z;
    const int cnt  = g_cnt[e];
    const int row0 = blockIdx.y * 128;
    if (row0 >= cnt) return;

    const int off  = g_off[e];
    const int n0   = blockIdx.x * 64;
    const int tid  = threadIdx.x;
    const int lane = tid & 31;
    const int wid  = tid >> 5;
    const int wm   = wid & 3;       // warp row (4)
    const int wn   = wid >> 2;      // warp col (2)
    const int gq   = lane >> 2;     // group id 0..7
    const int tq   = lane & 3;      // thread-in-group 0..3

    const float* __restrict__ Asrc = (MODE == 0) ? Xin : g_h;
    float*       __restrict__ Out  = (MODE == 0) ? g_h : g_y2;

    // --- per-thread A staging rows (fixed across K loop) ---
    const int ar  = tid >> 3;    // 0..31 row within 32-row pass
    const int akq = tid & 7;     // float4 index along K within 32
    const float4* aptr[4];
    bool aval[4];
#pragma unroll
    for (int p = 0; p < 4; ++p) {
        int lrow = p * 32 + ar;
        int grow = row0 + lrow;
        bool v = grow < cnt;
        aval[p] = v;
        size_t base = 0;
        if (v) {
            if (MODE == 0) base = (size_t)g_rowtok[off + grow] * KTOT;
            else           base = (size_t)(off + grow) * KTOT;
        }
        aptr[p] = reinterpret_cast<const float4*>(Asrc + base) + akq;
    }
    const float* wbase = Wt + (size_t)e * KTOT * NTOT + n0;

    float4 stA[4];
    float4 stB[2];

    auto ldg_tile = [&](int kt) {
#pragma unroll
        for (int p = 0; p < 4; ++p)
            stA[p] = aval[p] ? aptr[p][kt * 8] : make_float4(0.f, 0.f, 0.f, 0.f);
#pragma unroll
        for (int j = 0; j < 2; ++j) {
            int fi  = j * 256 + tid;
            int bkk = fi >> 4;
            int bnq = fi & 15;
            stB[j] = *reinterpret_cast<const float4*>(
                wbase + (size_t)(kt * 32 + bkk) * NTOT + bnq * 4);
        }
    };
    auto sts_tile = [&]() {
#pragma unroll
        for (int p = 0; p < 4; ++p) {
            int lrow = p * 32 + ar;
            uint4 u;
            u.x = f2tf32(stA[p].x); u.y = f2tf32(stA[p].y);
            u.z = f2tf32(stA[p].z); u.w = f2tf32(stA[p].w);
            *reinterpret_cast<uint4*>(&As[lrow * 36 + akq * 4]) = u;
        }
#pragma unroll
        for (int j = 0; j < 2; ++j) {
            int fi  = j * 256 + tid;
            int bkk = fi >> 4;
            int bnq = fi & 15;
            uint4 u;
            u.x = f2tf32(stB[j].x); u.y = f2tf32(stB[j].y);
            u.z = f2tf32(stB[j].z); u.w = f2tf32(stB[j].w);
            *reinterpret_cast<uint4*>(&Bs[bkk * 72 + bnq * 4]) = u;
        }
    };

    float acc[2][4][4];
#pragma unroll
    for (int mi = 0; mi < 2; ++mi)
#pragma unroll
        for (int ni = 0; ni < 4; ++ni)
#pragma unroll
            for (int q = 0; q < 4; ++q) acc[mi][ni][q] = 0.f;

    constexpr int KT = KTOT / 32;
    ldg_tile(0);
    sts_tile();
    __syncthreads();

    for (int kt = 0; kt < KT; ++kt) {
        if (kt + 1 < KT) ldg_tile(kt + 1);  // prefetch next tile into regs

#pragma unroll
        for (int kk = 0; kk < 32; kk += 8) {
            uint32_t af[2][4], bf[4][2];
#pragma unroll
            for (int mi = 0; mi < 2; ++mi) {
                int r = wm * 32 + mi * 16 + gq;
                af[mi][0] = As[r * 36 + kk + tq];
                af[mi][1] = As[(r + 8) * 36 + kk + tq];
                af[mi][2] = As[r * 36 + kk + tq + 4];
                af[mi][3] = As[(r + 8) * 36 + kk + tq + 4];
            }
#pragma unroll
            for (int ni = 0; ni < 4; ++ni) {
                int c = wn * 32 + ni * 8 + gq;
                bf[ni][0] = Bs[(kk + tq) * 72 + c];
                bf[ni][1] = Bs[(kk + tq + 4) * 72 + c];
            }
#pragma unroll
            for (int mi = 0; mi < 2; ++mi)
#pragma unroll
                for (int ni = 0; ni < 4; ++ni)
                    mma_tf32(acc[mi][ni], af[mi], bf[ni]);
        }

        if (kt + 1 < KT) {
            __syncthreads();
            sts_tile();
            __syncthreads();
        }
    }

    // ------------------------------ epilogue -------------------------------
    const float* bp = bias + (size_t)e * NTOT;
#pragma unroll
    for (int mi = 0; mi < 2; ++mi) {
#pragma unroll
        for (int rr = 0; rr < 2; ++rr) {
            int lrow = row0 + wm * 32 + mi * 16 + gq + rr * 8;
            if (lrow < cnt) {
                float* op = Out + (size_t)(off + lrow) * NTOT;
#pragma unroll
                for (int ni = 0; ni < 4; ++ni) {
                    int c = n0 + wn * 32 + ni * 8 + tq * 2;
                    float v0 = acc[mi][ni][rr * 2 + 0] + bp[c];
                    float v1 = acc[mi][ni][rr * 2 + 1] + bp[c + 1];
                    if (MODE == 0) {  // exact GELU (erf), matches approximate=False
                        v0 = 0.5f * v0 * (1.f + erff(v0 * 0.70710678118654752f));
                        v1 = 0.5f * v1 * (1.f + erff(v1 * 0.70710678118654752f));
                    }
                    *reinterpret_cast<float2*>(op + c) = make_float2(v0, v1);
                }
            }
        }
    }
}

// ------------------------------- combine ------------------------------------
// out[t, :] = wa[2t] * y2[slot(2t), :] + wa[2t+1] * y2[slot(2t+1), :]
// Fixed two-term sum per token -> bitwise deterministic, no atomics.
__global__ void k_combine(float* __restrict__ out) {
    int i = blockIdx.x * 256 + threadIdx.x;   // over T * (DM/4)
    if (i >= kT * (kDM / 4)) return;
    int t  = i >> 7;         // DM/4 = 128
    int d4 = i & 127;
    int a0 = t * 2, a1 = t * 2 + 1;
    float w0 = g_wa[a0], w1 = g_wa[a1];
    const float4 v0 = reinterpret_cast<const float4*>(g_y2 + (size_t)g_slot[a0] * kDM)[d4];
    const float4 v1 = reinterpret_cast<const float4*>(g_y2 + (size_t)g_slot[a1] * kDM)[d4];
    float4 r;
    r.x = w0 * v0.x + w1 * v1.x;
    r.y = w0 * v0.y + w1 * v1.y;
    r.z = w0 * v0.z + w1 * v1.z;
    r.w = w0 * v0.w + w1 * v1.w;
    reinterpret_cast<float4*>(out)[i] = r;
}

// ------------------------------- launch --------------------------------------
extern "C" void kernel_launch(void* const* d_in, const int* in_sizes, int n_in,
                              void* d_out, int out_size) {
    const float* hidden = (const float*)d_in[0];  // [8,1024,512]
    const int*   cat    = (const int*)  d_in[1];  // [8,1024,2]
    const int*   sub    = (const int*)  d_in[2];  // [8,1024,2]
    const float* wts    = (const float*)d_in[3];  // [8,1024,2]
    const float* W1     = (const float*)d_in[4];  // [64,512,2048]
    const float* b1     = (const float*)d_in[5];  // [64,2048]
    const float* W2     = (const float*)d_in[6];  // [64,2048,512]
    const float* b2     = (const float*)d_in[7];  // [64,512]
    float*       out    = (float*)d_out;          // [8,1024,512]

    (void)in_sizes; (void)n_in; (void)out_size;

    k_zero  <<<1, 64>>>();
    k_count <<<kA / 256, 256>>>(cat, sub);
    k_scan  <<<1, 32>>>();
    k_assign<<<kA / 256, 256>>>(wts);

    // GEMM1: rows x 512 @ 512 x 2048 (+GELU) -> g_h
    dim3 g1(kDF / 64, kCAP / 128, kE);
    k_gemm<kDM, kDF, 0><<<g1, 256>>>(hidden, W1, b1);

    // GEMM2: rows x 2048 @ 2048 x 512 -> g_y2
    dim3 g2(kDM / 64, kCAP / 128, kE);
    k_gemm<kDF, kDM, 1><<<g2, 256>>>(nullptr, W2, b2);

    // Combine: per-token weighted sum of its two expert outputs
    int ncomb = kT * (kDM / 4);
    k_combine<<<(ncomb + 255) / 256, 256>>>(out);
}